// round 2
// baseline (speedup 1.0000x reference)
#include <cuda_runtime.h>
#include <math.h>

// Problem constants
#define NB 4
#define NH 16
#define LSEQ 2048
#define DH 64
#define NBH (NB*NH)          // 64
#define BM 64                // q rows per block
#define BN 64                // k cols per tile
#define QTILES (LSEQ/BM)     // 32
#define KTILES (LSEQ/BN)     // 32

static constexpr float INV_TEMP = 0.125f;  // 1/8
static constexpr size_t OUT_ELEMS  = (size_t)NBH * LSEQ * DH * 2;   // 16,777,216
static constexpr size_t ATTN_ELEMS = (size_t)NBH * LSEQ * LSEQ;     // 268,435,456

// inverse row sums for the attn normalization kernel
__device__ float g_inv_rowsum[NBH * LSEQ];

// ---- shared memory layout (floats) ----
// Transposed+swizzled Q,K (+ Karatsuba combos): [d][row] with 16B-chunk XOR swizzle
// Row-major+swizzled V, P
#define SQ_R 0
#define SQ_I (SQ_R + 64*64)
#define SQ_S (SQ_I + 64*64)   // (qr + qi) / T
#define SK_R (SQ_S + 64*64)
#define SK_I (SK_R + 64*64)
#define SK_D (SK_I + 64*64)   // kr - ki
#define SV_R (SK_D + 64*64)
#define SV_I (SV_R + 64*64)
#define SP   (SV_I + 64*64)
#define SINV (SP + 64*64)
#define SMEM_FLOATS (SINV + 64)
#define SMEM_BYTES (SMEM_FLOATS * 4)

// chunk-swizzled index: float offset of 16B chunk `c` (0..15) in row `d` (0..63)
__device__ __forceinline__ int xidx(int d, int c) {
    return (d << 6) + (((c ^ d) & 15) << 2);
}

// Load two 64x64 tiles (real/imag), transpose into smem [d][row] with swizzle,
// also writing the Karatsuba combination tile: comb = r*cr + i*ci.
// g must already point at the tile origin (row stride = DH).
__device__ __forceinline__ void load_tile_T2(const float* __restrict__ gr,
                                             const float* __restrict__ gi,
                                             float* __restrict__ s_r,
                                             float* __restrict__ s_i,
                                             float* __restrict__ s_c,
                                             int row_t, int col_t,
                                             float scale, float cr, float ci) {
    float4 ggr[4], ggi[4];
#pragma unroll
    for (int rr = 0; rr < 4; ++rr) {
        ggr[rr] = *(const float4*)(gr + (size_t)(row_t * 4 + rr) * DH + col_t * 4);
        ggi[rr] = *(const float4*)(gi + (size_t)(row_t * 4 + rr) * DH + col_t * 4);
    }
#pragma unroll
    for (int j = 0; j < 4; ++j) {
        int d = col_t * 4 + j;
        float4 tr, ti, tc;
        float r0 = ((const float*)&ggr[0])[j] * scale;
        float r1 = ((const float*)&ggr[1])[j] * scale;
        float r2 = ((const float*)&ggr[2])[j] * scale;
        float r3 = ((const float*)&ggr[3])[j] * scale;
        float i0 = ((const float*)&ggi[0])[j] * scale;
        float i1 = ((const float*)&ggi[1])[j] * scale;
        float i2 = ((const float*)&ggi[2])[j] * scale;
        float i3 = ((const float*)&ggi[3])[j] * scale;
        tr = make_float4(r0, r1, r2, r3);
        ti = make_float4(i0, i1, i2, i3);
        tc = make_float4(fmaf(cr, r0, ci * i0), fmaf(cr, r1, ci * i1),
                         fmaf(cr, r2, ci * i2), fmaf(cr, r3, ci * i3));
        const int o = xidx(d, row_t);
        *(float4*)(s_r + o) = tr;
        *(float4*)(s_i + o) = ti;
        *(float4*)(s_c + o) = tc;
    }
}

// Load a 64x64 tile row-major into smem [row][d] with swizzle on d-chunks.
__device__ __forceinline__ void load_tile_V(const float* __restrict__ g, float* __restrict__ s,
                                            int row_t, int col_t) {
#pragma unroll
    for (int rr = 0; rr < 4; ++rr) {
        int r = row_t * 4 + rr;
        float4 v = *(const float4*)(g + (size_t)r * DH + col_t * 4);
        *(float4*)(s + xidx(r, col_t)) = v;
    }
}

__global__ void __launch_bounds__(256, 1)
cattn_kernel(const float* __restrict__ Qr, const float* __restrict__ Qi,
             const float* __restrict__ Kr, const float* __restrict__ Ki,
             const float* __restrict__ Vr, const float* __restrict__ Vi,
             float* __restrict__ Out, float* __restrict__ Attn,
             int write_out, int write_attn) {
    extern __shared__ float sm[];

    const int tid   = threadIdx.x;
    const int row_t = tid >> 4;    // 0..15
    const int col_t = tid & 15;    // 0..15
    const int r0    = row_t * 4;
    const int c0    = col_t * 4;

    const int bh = blockIdx.y;
    const int q0 = blockIdx.x * BM;
    const size_t base = (size_t)bh * LSEQ * DH;

    // ---- load Q tiles (transposed, swizzled, scaled by 1/T) + qs = qr+qi ----
    load_tile_T2(Qr + base + (size_t)q0 * DH, Qi + base + (size_t)q0 * DH,
                 sm + SQ_R, sm + SQ_I, sm + SQ_S, row_t, col_t,
                 INV_TEMP, 1.0f, 1.0f);

    float o_r[4][4], o_i[4][4];
#pragma unroll
    for (int a = 0; a < 4; ++a)
#pragma unroll
        for (int b = 0; b < 4; ++b) { o_r[a][b] = 0.f; o_i[a][b] = 0.f; }
    float rs[4] = {0.f, 0.f, 0.f, 0.f};

    // precomputed p-tile addressing
    const float* psrow[4];
    int rx[4];
#pragma unroll
    for (int a = 0; a < 4; ++a) {
        psrow[a] = sm + SP + ((r0 + a) << 6);
        rx[a] = (r0 + a) & 15;
    }

    for (int kt = 0; kt < KTILES; ++kt) {
        __syncthreads();  // previous tile's smem consumers done
        const size_t kbase = base + (size_t)kt * BN * DH;
        // K tiles + kd = kr - ki
        load_tile_T2(Kr + kbase, Ki + kbase,
                     sm + SK_R, sm + SK_I, sm + SK_D, row_t, col_t,
                     1.0f, 1.0f, -1.0f);
        load_tile_V(Vr + kbase, sm + SV_R, row_t, col_t);
        load_tile_V(Vi + kbase, sm + SV_I, row_t, col_t);
        __syncthreads();

        // ---- S = (Q/T) @ conj(K)^H via 3-mult Karatsuba ----
        // m1 = qr.kr, m2 = qi.ki, m3 = (qr+qi).(kr-ki)
        // s_r = m1 + m2 ; s_i = m3 - m1 + m2
        float m1[4][4], m2[4][4], m3[4][4];
#pragma unroll
        for (int a = 0; a < 4; ++a)
#pragma unroll
            for (int b = 0; b < 4; ++b) { m1[a][b] = 0.f; m2[a][b] = 0.f; m3[a][b] = 0.f; }

#pragma unroll 4
        for (int kk = 0; kk < 64; ++kk) {
            const int oq = xidx(kk, row_t);
            const int ok = xidx(kk, col_t);
            const float4 aqr = *(const float4*)(sm + SQ_R + oq);
            const float4 aqi = *(const float4*)(sm + SQ_I + oq);
            const float4 aqs = *(const float4*)(sm + SQ_S + oq);
            const float4 bkr = *(const float4*)(sm + SK_R + ok);
            const float4 bki = *(const float4*)(sm + SK_I + ok);
            const float4 bkd = *(const float4*)(sm + SK_D + ok);
            const float qra[4] = {aqr.x, aqr.y, aqr.z, aqr.w};
            const float qia[4] = {aqi.x, aqi.y, aqi.z, aqi.w};
            const float qsa[4] = {aqs.x, aqs.y, aqs.z, aqs.w};
            const float krb[4] = {bkr.x, bkr.y, bkr.z, bkr.w};
            const float kib[4] = {bki.x, bki.y, bki.z, bki.w};
            const float kdb[4] = {bkd.x, bkd.y, bkd.z, bkd.w};
#pragma unroll
            for (int a = 0; a < 4; ++a)
#pragma unroll
                for (int b = 0; b < 4; ++b) {
                    m1[a][b] = fmaf(qra[a], krb[b], m1[a][b]);
                    m2[a][b] = fmaf(qia[a], kib[b], m2[a][b]);
                    m3[a][b] = fmaf(qsa[a], kdb[b], m3[a][b]);
                }
        }

        // ---- p = exp(|s|)  (no max subtraction: |s| <= ~10, fp32-safe) ----
        float pv[4][4];
#pragma unroll
        for (int a = 0; a < 4; ++a)
#pragma unroll
            for (int b = 0; b < 4; ++b) {
                float sr = m1[a][b] + m2[a][b];
                float si = (m3[a][b] + m2[a][b]) - m1[a][b];
                float mag2 = fmaf(sr, sr, si * si);
                pv[a][b] = __expf(sqrtf(mag2));
            }

        // unnormalized attn write (normalized later by norm_kernel)
        if (write_attn) {
#pragma unroll
            for (int a = 0; a < 4; ++a) {
                size_t arow = ((size_t)bh * LSEQ + q0 + r0 + a) * LSEQ + (size_t)kt * BN + c0;
                *(float4*)(Attn + arow) = make_float4(pv[a][0], pv[a][1], pv[a][2], pv[a][3]);
            }
        }

        // row-sum accumulate: butterfly over the 16 lanes sharing this row group
#pragma unroll
        for (int a = 0; a < 4; ++a) {
            float v = pv[a][0] + pv[a][1] + pv[a][2] + pv[a][3];
            v += __shfl_xor_sync(0xffffffffu, v, 1, 16);
            v += __shfl_xor_sync(0xffffffffu, v, 2, 16);
            v += __shfl_xor_sync(0xffffffffu, v, 4, 16);
            v += __shfl_xor_sync(0xffffffffu, v, 8, 16);
            rs[a] += v;
        }

        // stage p tile to smem (writers == readers within the same warp)
#pragma unroll
        for (int a = 0; a < 4; ++a)
            *(float4*)(sm + SP + xidx(r0 + a, col_t)) =
                make_float4(pv[a][0], pv[a][1], pv[a][2], pv[a][3]);
        __syncwarp();

        // ---- O += p @ V  (real and imag) ----
#pragma unroll 8
        for (int kk = 0; kk < 64; ++kk) {
            const int ov = xidx(kk, col_t);
            const float4 vr4 = *(const float4*)(sm + SV_R + ov);
            const float4 vi4 = *(const float4*)(sm + SV_I + ov);
            const int kk4 = kk >> 2, kkm = kk & 3;
#pragma unroll
            for (int a = 0; a < 4; ++a) {
                const float p = psrow[a][((kk4 ^ rx[a]) << 2) + kkm];
                o_r[a][0] = fmaf(p, vr4.x, o_r[a][0]);
                o_r[a][1] = fmaf(p, vr4.y, o_r[a][1]);
                o_r[a][2] = fmaf(p, vr4.z, o_r[a][2]);
                o_r[a][3] = fmaf(p, vr4.w, o_r[a][3]);
                o_i[a][0] = fmaf(p, vi4.x, o_i[a][0]);
                o_i[a][1] = fmaf(p, vi4.y, o_i[a][1]);
                o_i[a][2] = fmaf(p, vi4.z, o_i[a][2]);
                o_i[a][3] = fmaf(p, vi4.w, o_i[a][3]);
            }
        }
    }

    // ---- finalize: 1/rowsum -> smem + global; normalize O; write output ----
    if (col_t == 0) {
#pragma unroll
        for (int a = 0; a < 4; ++a) {
            float inv = 1.0f / rs[a];
            sm[SINV + r0 + a] = inv;
            g_inv_rowsum[(size_t)bh * LSEQ + q0 + r0 + a] = inv;
        }
    }
    __syncthreads();

    if (write_out) {
#pragma unroll
        for (int a = 0; a < 4; ++a) {
            const float inv = sm[SINV + r0 + a];
            size_t ob = ((size_t)bh * LSEQ + q0 + r0 + a) * (DH * 2) + (size_t)c0 * 2;
            float4 o1 = make_float4(o_r[a][0] * inv, o_i[a][0] * inv,
                                    o_r[a][1] * inv, o_i[a][1] * inv);
            float4 o2 = make_float4(o_r[a][2] * inv, o_i[a][2] * inv,
                                    o_r[a][3] * inv, o_i[a][3] * inv);
            *(float4*)(Out + ob)     = o1;
            *(float4*)(Out + ob + 4) = o2;
        }
    }
}

// normalize attn in place: one block per (bh, q) row
__global__ void __launch_bounds__(256)
norm_kernel(float* __restrict__ Attn) {
    const size_t row = blockIdx.x;
    const float inv = g_inv_rowsum[row];
    float4* p = (float4*)(Attn + row * LSEQ);
    const int t = threadIdx.x;
#pragma unroll
    for (int i = 0; i < 2; ++i) {
        float4 v = p[t + i * 256];
        v.x *= inv; v.y *= inv; v.z *= inv; v.w *= inv;
        p[t + i * 256] = v;
    }
}

extern "C" void kernel_launch(void* const* d_in, const int* in_sizes, int n_in,
                              void* d_out, int out_size) {
    const float* Qr = (const float*)d_in[0];
    const float* Qi = (const float*)d_in[1];
    const float* Kr = (const float*)d_in[2];
    const float* Ki = (const float*)d_in[3];
    const float* Vr = (const float*)d_in[4];
    const float* Vi = (const float*)d_in[5];

    float* out = (float*)d_out;
    int write_out = 1, write_attn = 1;
    float* attn = out + OUT_ELEMS;

    const size_t os = (size_t)out_size;
    if (os >= OUT_ELEMS + ATTN_ELEMS) {
        // tuple (output, attn) concatenated
    } else if (os == ATTN_ELEMS) {
        write_out = 0;
        attn = out;
    } else {
        // output only
        write_attn = 0;
        attn = out;  // unused
    }

    cudaFuncSetAttribute(cattn_kernel, cudaFuncAttributeMaxDynamicSharedMemorySize, SMEM_BYTES);

    dim3 grid(QTILES, NBH);   // q-tiles fastest -> K/V of one (b,h) stay hot in L2
    cattn_kernel<<<grid, 256, SMEM_BYTES>>>(Qr, Qi, Kr, Ki, Vr, Vi,
                                            out, attn, write_out, write_attn);
    if (write_attn) {
        norm_kernel<<<NBH * LSEQ, 256>>>(attn);
    }
}

// round 3
// speedup vs baseline: 1.0009x; 1.0009x over previous
#include <cuda_runtime.h>
#include <math.h>

// Problem constants
#define NB 4
#define NH 16
#define LSEQ 2048
#define DH 64
#define NBH (NB*NH)          // 64
#define BM 64                // q rows per block
#define BN 64                // k cols per tile
#define QTILES (LSEQ/BM)     // 32
#define KTILES (LSEQ/BN)     // 32

static constexpr float INV_TEMP = 0.125f;  // 1/8
static constexpr size_t OUT_ELEMS  = (size_t)NBH * LSEQ * DH * 2;   // 16,777,216
static constexpr size_t ATTN_ELEMS = (size_t)NBH * LSEQ * LSEQ;     // 268,435,456

// inverse row sums for the attn normalization kernel
__device__ float g_inv_rowsum[NBH * LSEQ];

// ---- shared memory layout (floats) ----
// Transposed+swizzled Q,K (+ Karatsuba combos): [d][row] with 16B-chunk XOR swizzle
// Row-major+swizzled V, P
#define SQ_R 0
#define SQ_I (SQ_R + 64*64)
#define SQ_S (SQ_I + 64*64)   // (qr + qi) / T
#define SK_R (SQ_S + 64*64)
#define SK_I (SK_R + 64*64)
#define SK_D (SK_I + 64*64)   // kr - ki
#define SV_R (SK_D + 64*64)
#define SV_I (SV_R + 64*64)
#define SP   (SV_I + 64*64)
#define SINV (SP + 64*64)
#define SMEM_FLOATS (SINV + 64)
#define SMEM_BYTES (SMEM_FLOATS * 4)

// chunk-swizzled index: float offset of 16B chunk `c` (0..15) in row `d` (0..63)
__device__ __forceinline__ int xidx(int d, int c) {
    return (d << 6) + (((c ^ d) & 15) << 2);
}

// Load two 64x64 tiles (real/imag), transpose into smem [d][row] with swizzle,
// also writing the Karatsuba combination tile: comb = r*cr + i*ci.
// g must already point at the tile origin (row stride = DH).
__device__ __forceinline__ void load_tile_T2(const float* __restrict__ gr,
                                             const float* __restrict__ gi,
                                             float* __restrict__ s_r,
                                             float* __restrict__ s_i,
                                             float* __restrict__ s_c,
                                             int row_t, int col_t,
                                             float scale, float cr, float ci) {
    float4 ggr[4], ggi[4];
#pragma unroll
    for (int rr = 0; rr < 4; ++rr) {
        ggr[rr] = *(const float4*)(gr + (size_t)(row_t * 4 + rr) * DH + col_t * 4);
        ggi[rr] = *(const float4*)(gi + (size_t)(row_t * 4 + rr) * DH + col_t * 4);
    }
#pragma unroll
    for (int j = 0; j < 4; ++j) {
        int d = col_t * 4 + j;
        float4 tr, ti, tc;
        float r0 = ((const float*)&ggr[0])[j] * scale;
        float r1 = ((const float*)&ggr[1])[j] * scale;
        float r2 = ((const float*)&ggr[2])[j] * scale;
        float r3 = ((const float*)&ggr[3])[j] * scale;
        float i0 = ((const float*)&ggi[0])[j] * scale;
        float i1 = ((const float*)&ggi[1])[j] * scale;
        float i2 = ((const float*)&ggi[2])[j] * scale;
        float i3 = ((const float*)&ggi[3])[j] * scale;
        tr = make_float4(r0, r1, r2, r3);
        ti = make_float4(i0, i1, i2, i3);
        tc = make_float4(fmaf(cr, r0, ci * i0), fmaf(cr, r1, ci * i1),
                         fmaf(cr, r2, ci * i2), fmaf(cr, r3, ci * i3));
        const int o = xidx(d, row_t);
        *(float4*)(s_r + o) = tr;
        *(float4*)(s_i + o) = ti;
        *(float4*)(s_c + o) = tc;
    }
}

// Load a 64x64 tile row-major into smem [row][d] with swizzle on d-chunks.
__device__ __forceinline__ void load_tile_V(const float* __restrict__ g, float* __restrict__ s,
                                            int row_t, int col_t) {
#pragma unroll
    for (int rr = 0; rr < 4; ++rr) {
        int r = row_t * 4 + rr;
        float4 v = *(const float4*)(g + (size_t)r * DH + col_t * 4);
        *(float4*)(s + xidx(r, col_t)) = v;
    }
}

__global__ void __launch_bounds__(256, 1)
cattn_kernel(const float* __restrict__ Qr, const float* __restrict__ Qi,
             const float* __restrict__ Kr, const float* __restrict__ Ki,
             const float* __restrict__ Vr, const float* __restrict__ Vi,
             float* __restrict__ Out, float* __restrict__ Attn,
             int write_out, int write_attn) {
    extern __shared__ float sm[];

    const int tid   = threadIdx.x;
    const int row_t = tid >> 4;    // 0..15
    const int col_t = tid & 15;    // 0..15
    const int r0    = row_t * 4;
    const int c0    = col_t * 4;

    const int bh = blockIdx.y;
    const int q0 = blockIdx.x * BM;
    const size_t base = (size_t)bh * LSEQ * DH;

    // ---- load Q tiles (transposed, swizzled, scaled by 1/T) + qs = qr+qi ----
    load_tile_T2(Qr + base + (size_t)q0 * DH, Qi + base + (size_t)q0 * DH,
                 sm + SQ_R, sm + SQ_I, sm + SQ_S, row_t, col_t,
                 INV_TEMP, 1.0f, 1.0f);

    float o_r[4][4], o_i[4][4];
#pragma unroll
    for (int a = 0; a < 4; ++a)
#pragma unroll
        for (int b = 0; b < 4; ++b) { o_r[a][b] = 0.f; o_i[a][b] = 0.f; }
    float rs[4] = {0.f, 0.f, 0.f, 0.f};

    // precomputed p-tile addressing
    const float* psrow[4];
    int rx[4];
#pragma unroll
    for (int a = 0; a < 4; ++a) {
        psrow[a] = sm + SP + ((r0 + a) << 6);
        rx[a] = (r0 + a) & 15;
    }

    for (int kt = 0; kt < KTILES; ++kt) {
        __syncthreads();  // previous tile's smem consumers done
        const size_t kbase = base + (size_t)kt * BN * DH;
        // K tiles + kd = kr - ki
        load_tile_T2(Kr + kbase, Ki + kbase,
                     sm + SK_R, sm + SK_I, sm + SK_D, row_t, col_t,
                     1.0f, 1.0f, -1.0f);
        load_tile_V(Vr + kbase, sm + SV_R, row_t, col_t);
        load_tile_V(Vi + kbase, sm + SV_I, row_t, col_t);
        __syncthreads();

        // ---- S = (Q/T) @ conj(K)^H via 3-mult Karatsuba ----
        // m1 = qr.kr, m2 = qi.ki, m3 = (qr+qi).(kr-ki)
        // s_r = m1 + m2 ; s_i = m3 - m1 + m2
        float m1[4][4], m2[4][4], m3[4][4];
#pragma unroll
        for (int a = 0; a < 4; ++a)
#pragma unroll
            for (int b = 0; b < 4; ++b) { m1[a][b] = 0.f; m2[a][b] = 0.f; m3[a][b] = 0.f; }

#pragma unroll 4
        for (int kk = 0; kk < 64; ++kk) {
            const int oq = xidx(kk, row_t);
            const int ok = xidx(kk, col_t);
            const float4 aqr = *(const float4*)(sm + SQ_R + oq);
            const float4 aqi = *(const float4*)(sm + SQ_I + oq);
            const float4 aqs = *(const float4*)(sm + SQ_S + oq);
            const float4 bkr = *(const float4*)(sm + SK_R + ok);
            const float4 bki = *(const float4*)(sm + SK_I + ok);
            const float4 bkd = *(const float4*)(sm + SK_D + ok);
            const float qra[4] = {aqr.x, aqr.y, aqr.z, aqr.w};
            const float qia[4] = {aqi.x, aqi.y, aqi.z, aqi.w};
            const float qsa[4] = {aqs.x, aqs.y, aqs.z, aqs.w};
            const float krb[4] = {bkr.x, bkr.y, bkr.z, bkr.w};
            const float kib[4] = {bki.x, bki.y, bki.z, bki.w};
            const float kdb[4] = {bkd.x, bkd.y, bkd.z, bkd.w};
#pragma unroll
            for (int a = 0; a < 4; ++a)
#pragma unroll
                for (int b = 0; b < 4; ++b) {
                    m1[a][b] = fmaf(qra[a], krb[b], m1[a][b]);
                    m2[a][b] = fmaf(qia[a], kib[b], m2[a][b]);
                    m3[a][b] = fmaf(qsa[a], kdb[b], m3[a][b]);
                }
        }

        // ---- p = exp(|s|)  (no max subtraction: |s| <= ~10, fp32-safe) ----
        float pv[4][4];
#pragma unroll
        for (int a = 0; a < 4; ++a)
#pragma unroll
            for (int b = 0; b < 4; ++b) {
                float sr = m1[a][b] + m2[a][b];
                float si = (m3[a][b] + m2[a][b]) - m1[a][b];
                float mag2 = fmaf(sr, sr, si * si);
                pv[a][b] = __expf(sqrtf(mag2));
            }

        // unnormalized attn write (normalized later by norm_kernel)
        if (write_attn) {
#pragma unroll
            for (int a = 0; a < 4; ++a) {
                size_t arow = ((size_t)bh * LSEQ + q0 + r0 + a) * LSEQ + (size_t)kt * BN + c0;
                *(float4*)(Attn + arow) = make_float4(pv[a][0], pv[a][1], pv[a][2], pv[a][3]);
            }
        }

        // row-sum accumulate: butterfly over the 16 lanes sharing this row group
#pragma unroll
        for (int a = 0; a < 4; ++a) {
            float v = pv[a][0] + pv[a][1] + pv[a][2] + pv[a][3];
            v += __shfl_xor_sync(0xffffffffu, v, 1, 16);
            v += __shfl_xor_sync(0xffffffffu, v, 2, 16);
            v += __shfl_xor_sync(0xffffffffu, v, 4, 16);
            v += __shfl_xor_sync(0xffffffffu, v, 8, 16);
            rs[a] += v;
        }

        // stage p tile to smem (writers == readers within the same warp)
#pragma unroll
        for (int a = 0; a < 4; ++a)
            *(float4*)(sm + SP + xidx(r0 + a, col_t)) =
                make_float4(pv[a][0], pv[a][1], pv[a][2], pv[a][3]);
        __syncwarp();

        // ---- O += p @ V  (real and imag) ----
#pragma unroll 8
        for (int kk = 0; kk < 64; ++kk) {
            const int ov = xidx(kk, col_t);
            const float4 vr4 = *(const float4*)(sm + SV_R + ov);
            const float4 vi4 = *(const float4*)(sm + SV_I + ov);
            const int kk4 = kk >> 2, kkm = kk & 3;
#pragma unroll
            for (int a = 0; a < 4; ++a) {
                const float p = psrow[a][((kk4 ^ rx[a]) << 2) + kkm];
                o_r[a][0] = fmaf(p, vr4.x, o_r[a][0]);
                o_r[a][1] = fmaf(p, vr4.y, o_r[a][1]);
                o_r[a][2] = fmaf(p, vr4.z, o_r[a][2]);
                o_r[a][3] = fmaf(p, vr4.w, o_r[a][3]);
                o_i[a][0] = fmaf(p, vi4.x, o_i[a][0]);
                o_i[a][1] = fmaf(p, vi4.y, o_i[a][1]);
                o_i[a][2] = fmaf(p, vi4.z, o_i[a][2]);
                o_i[a][3] = fmaf(p, vi4.w, o_i[a][3]);
            }
        }
    }

    // ---- finalize: 1/rowsum -> smem + global; normalize O; write output ----
    if (col_t == 0) {
#pragma unroll
        for (int a = 0; a < 4; ++a) {
            float inv = 1.0f / rs[a];
            sm[SINV + r0 + a] = inv;
            g_inv_rowsum[(size_t)bh * LSEQ + q0 + r0 + a] = inv;
        }
    }
    __syncthreads();

    if (write_out) {
#pragma unroll
        for (int a = 0; a < 4; ++a) {
            const float inv = sm[SINV + r0 + a];
            size_t ob = ((size_t)bh * LSEQ + q0 + r0 + a) * (DH * 2) + (size_t)c0 * 2;
            float4 o1 = make_float4(o_r[a][0] * inv, o_i[a][0] * inv,
                                    o_r[a][1] * inv, o_i[a][1] * inv);
            float4 o2 = make_float4(o_r[a][2] * inv, o_i[a][2] * inv,
                                    o_r[a][3] * inv, o_i[a][3] * inv);
            *(float4*)(Out + ob)     = o1;
            *(float4*)(Out + ob + 4) = o2;
        }
    }
}

// normalize attn in place: one block per (bh, q) row
__global__ void __launch_bounds__(256)
norm_kernel(float* __restrict__ Attn) {
    const size_t row = blockIdx.x;
    const float inv = g_inv_rowsum[row];
    float4* p = (float4*)(Attn + row * LSEQ);
    const int t = threadIdx.x;
#pragma unroll
    for (int i = 0; i < 2; ++i) {
        float4 v = p[t + i * 256];
        v.x *= inv; v.y *= inv; v.z *= inv; v.w *= inv;
        p[t + i * 256] = v;
    }
}

extern "C" void kernel_launch(void* const* d_in, const int* in_sizes, int n_in,
                              void* d_out, int out_size) {
    const float* Qr = (const float*)d_in[0];
    const float* Qi = (const float*)d_in[1];
    const float* Kr = (const float*)d_in[2];
    const float* Ki = (const float*)d_in[3];
    const float* Vr = (const float*)d_in[4];
    const float* Vi = (const float*)d_in[5];

    float* out = (float*)d_out;
    int write_out = 1, write_attn = 1;
    float* attn = out + OUT_ELEMS;

    const size_t os = (size_t)out_size;
    if (os >= OUT_ELEMS + ATTN_ELEMS) {
        // tuple (output, attn) concatenated
    } else if (os == ATTN_ELEMS) {
        write_out = 0;
        attn = out;
    } else {
        // output only
        write_attn = 0;
        attn = out;  // unused
    }

    cudaFuncSetAttribute(cattn_kernel, cudaFuncAttributeMaxDynamicSharedMemorySize, SMEM_BYTES);

    dim3 grid(QTILES, NBH);   // q-tiles fastest -> K/V of one (b,h) stay hot in L2
    cattn_kernel<<<grid, 256, SMEM_BYTES>>>(Qr, Qi, Kr, Ki, Vr, Vi,
                                            out, attn, write_out, write_attn);
    if (write_attn) {
        norm_kernel<<<NBH * LSEQ, 256>>>(attn);
    }
}

// round 6
// speedup vs baseline: 3.2104x; 3.2076x over previous
#include <cuda_runtime.h>
#include <cuda_fp16.h>
#include <stdint.h>
#include <math.h>

// ---------------- problem constants ----------------
#define NBH 64
#define LSEQ 2048
#define DH 64
#define BM 64                  // q rows per CTA
#define BNK 64                 // k tokens per tile
#define KT (LSEQ/BNK)          // 32
#define QT (LSEQ/BM)           // 32
static constexpr float INV_TEMP = 0.125f;
static constexpr size_t OUT_ELEMS  = (size_t)NBH * LSEQ * DH * 2;   // 16,777,216
static constexpr size_t ATTN_ELEMS = (size_t)NBH * LSEQ * LSEQ;     // 268,435,456

__device__ float g_inv_rowsum[NBH * LSEQ];

// ---------------- smem layout (bytes), fp16 tiles, 128B rows, SW128 swizzle ----
#define OFF_QR   0             // 64 x 64 fp16 = 8192
#define OFF_QI   8192
#define OFF_ST0  16384         // stage: KR | KI | VR | VI (8192 each)
#define OFF_ST1  49152
#define STG_KR   0
#define STG_KI   8192
#define STG_VR   16384
#define STG_VI   24576
#define SMEM_BYTES 81920

#define SW(o) ((o) ^ (((o) >> 3) & 0x70))

// ---------------- PTX helpers (sm_80-class: valid on sm_100 base target) ----
__device__ __forceinline__ uint32_t smem_u32(const void* p) {
    uint32_t a;
    asm("{ .reg .u64 t; cvta.to.shared.u64 t, %1; cvt.u32.u64 %0, t; }" : "=r"(a) : "l"(p));
    return a;
}
__device__ __forceinline__ void ldsm_x2(uint32_t& r0, uint32_t& r1, uint32_t addr) {
    asm volatile("ldmatrix.sync.aligned.m8n8.x2.shared.b16 {%0,%1}, [%2];"
                 : "=r"(r0), "=r"(r1) : "r"(addr));
}
__device__ __forceinline__ void ldsm_x2t(uint32_t& r0, uint32_t& r1, uint32_t addr) {
    asm volatile("ldmatrix.sync.aligned.m8n8.x2.trans.shared.b16 {%0,%1}, [%2];"
                 : "=r"(r0), "=r"(r1) : "r"(addr));
}
__device__ __forceinline__ void ldsm_x4(uint32_t* r, uint32_t addr) {
    asm volatile("ldmatrix.sync.aligned.m8n8.x4.shared.b16 {%0,%1,%2,%3}, [%4];"
                 : "=r"(r[0]), "=r"(r[1]), "=r"(r[2]), "=r"(r[3]) : "r"(addr));
}
__device__ __forceinline__ void mma_f16(float* d, const uint32_t* a, uint32_t b0, uint32_t b1) {
    asm volatile(
        "mma.sync.aligned.m16n8k16.row.col.f32.f16.f16.f32 "
        "{%0,%1,%2,%3}, {%4,%5,%6,%7}, {%8,%9}, {%0,%1,%2,%3};"
        : "+f"(d[0]), "+f"(d[1]), "+f"(d[2]), "+f"(d[3])
        : "r"(a[0]), "r"(a[1]), "r"(a[2]), "r"(a[3]), "r"(b0), "r"(b1));
}
__device__ __forceinline__ uint32_t packh2(float x, float y) {
    __half2 h = __floats2half2_rn(x, y);
    return *reinterpret_cast<uint32_t*>(&h);
}
__device__ __forceinline__ float sqrt_approx(float x) {
    float r;
    asm("sqrt.approx.f32 %0, %1;" : "=f"(r) : "f"(x));
    return r;
}

// convert one 64-wide fp32 half-row (32 floats) to fp16 into swizzled smem
__device__ __forceinline__ void cvt_row(const float* __restrict__ g, char* __restrict__ dst,
                                        int row, int h, float scale) {
    const float4* gp = (const float4*)(g + h * 32);
    float4 f[8];
#pragma unroll
    for (int j = 0; j < 8; ++j) f[j] = gp[j];
#pragma unroll
    for (int c = 0; c < 4; ++c) {
        uint4 v;
        v.x = packh2(f[2*c].x * scale, f[2*c].y * scale);
        v.y = packh2(f[2*c].z * scale, f[2*c].w * scale);
        v.z = packh2(f[2*c+1].x * scale, f[2*c+1].y * scale);
        v.w = packh2(f[2*c+1].z * scale, f[2*c+1].w * scale);
        *(uint4*)(dst + SW(row * 128 + h * 64 + c * 16)) = v;
    }
}

// ---------------- main kernel ----------------
__global__ void __launch_bounds__(128, 2)
cattn_mma_kernel(const float* __restrict__ Qr, const float* __restrict__ Qi,
                 const float* __restrict__ Kr, const float* __restrict__ Ki,
                 const float* __restrict__ Vr, const float* __restrict__ Vi,
                 float* __restrict__ Out, float* __restrict__ Attn,
                 int write_out, int write_attn) {
    extern __shared__ char smc[];
    const uint32_t smb = smem_u32(smc);
    const int tid = threadIdx.x, w = tid >> 5, l = tid & 31;
    const int bh = blockIdx.y;
    const int q0 = blockIdx.x * BM;
    const size_t base = (size_t)bh * LSEQ * DH;

    // ---- load Q (fp16, swizzled, scaled) and first K/V stage ----
    {
        const int row = tid >> 1, h = tid & 1;
        cvt_row(Qr + base + (size_t)(q0 + row) * DH, smc + OFF_QR, row, h, INV_TEMP);
        cvt_row(Qi + base + (size_t)(q0 + row) * DH, smc + OFF_QI, row, h, INV_TEMP);
        const size_t kb0 = base + (size_t)row * DH;
        cvt_row(Kr + kb0, smc + OFF_ST0 + STG_KR, row, h, 1.0f);
        cvt_row(Ki + kb0, smc + OFF_ST0 + STG_KI, row, h, 1.0f);
        cvt_row(Vr + kb0, smc + OFF_ST0 + STG_VR, row, h, 1.0f);
        cvt_row(Vi + kb0, smc + OFF_ST0 + STG_VI, row, h, 1.0f);
    }
    __syncthreads();

    // ---- Q fragments (persist across all tiles) ----
    uint32_t qr[4][4], qi[4][4];
    {
        const int rowQ = w * 16 + (l & 15);
        const int hq = (l >> 4) & 1;
        const int rswz = (rowQ & 7) * 16;
#pragma unroll
        for (int kb = 0; kb < 4; ++kb) {
            const uint32_t off = rowQ * 128 + ((kb * 32 + hq * 16) ^ rswz);
            ldsm_x4(qr[kb], smb + OFF_QR + off);
            ldsm_x4(qi[kb], smb + OFF_QI + off);
        }
    }

    // per-lane ldmatrix address parts
    const uint32_t rowK = (l & 7) * 128 + ((l >> 3) & 1) * 16;   // K: lanes 0-15 used
    const uint32_t swzK = (l & 7) * 16;
    const uint32_t rowV = (l & 15) * 128;                        // V: lanes 0-15 used
    const uint32_t swzV = (l & 7) * 16;

    // persistent accumulators
    float o_r[8][4], o_i[8][4];
#pragma unroll
    for (int nb = 0; nb < 8; ++nb)
#pragma unroll
        for (int j = 0; j < 4; ++j) { o_r[nb][j] = 0.f; o_i[nb][j] = 0.f; }
    float rs0 = 0.f, rs1 = 0.f;

    const int arow0 = q0 + w * 16 + (l >> 2);
    float* attn_r0 = Attn + ((size_t)bh * LSEQ + arow0) * LSEQ + 2 * (l & 3);
    float* attn_r1 = attn_r0 + 8 * LSEQ;

    for (int kt = 0; kt < KT; ++kt) {
        const uint32_t cur = (kt & 1) ? OFF_ST1 : OFF_ST0;
        const uint32_t nxt = (kt & 1) ? OFF_ST0 : OFF_ST1;

        // prefetch next stage (fp32 -> fp16) while computing on cur
        if (kt < KT - 1) {
            const int row = tid >> 1, h = tid & 1;
            const size_t kb = base + (size_t)(kt + 1) * BNK * DH + (size_t)row * DH;
            cvt_row(Kr + kb, smc + nxt + STG_KR, row, h, 1.0f);
            cvt_row(Ki + kb, smc + nxt + STG_KI, row, h, 1.0f);
            cvt_row(Vr + kb, smc + nxt + STG_VR, row, h, 1.0f);
            cvt_row(Vi + kb, smc + nxt + STG_VI, row, h, 1.0f);
        }

        // ---- S = (Q/T) @ conj(K)^H : sr = qr.kr + qi.ki ; si = qi.kr - qr.ki ----
        float sr[8][4], si[8][4];
#pragma unroll
        for (int nb = 0; nb < 8; ++nb)
#pragma unroll
            for (int j = 0; j < 4; ++j) { sr[nb][j] = 0.f; si[nb][j] = 0.f; }

        const uint32_t krb = smb + cur + STG_KR;
        const uint32_t kib = smb + cur + STG_KI;
#pragma unroll
        for (int kb = 0; kb < 4; ++kb) {
            const uint32_t koff = (kb * 32 + rowK) ^ swzK;
#pragma unroll
            for (int nb = 0; nb < 8; ++nb) {
                uint32_t kr0, kr1, ki0, ki1;
                ldsm_x2(kr0, kr1, krb + nb * 1024 + koff);
                ldsm_x2(ki0, ki1, kib + nb * 1024 + koff);
                mma_f16(sr[nb], qr[kb], kr0, kr1);
                mma_f16(sr[nb], qi[kb], ki0, ki1);
                mma_f16(si[nb], qi[kb], kr0, kr1);
                const uint32_t kn0 = ki0 ^ 0x80008000u, kn1 = ki1 ^ 0x80008000u;
                mma_f16(si[nb], qr[kb], kn0, kn1);
            }
        }

        // ---- p = exp(|s|) (fp32, no max-subtraction: |s| small) ----
        float p[8][4];
#pragma unroll
        for (int nb = 0; nb < 8; ++nb)
#pragma unroll
            for (int j = 0; j < 4; ++j) {
                const float m2 = fmaf(sr[nb][j], sr[nb][j], si[nb][j] * si[nb][j]);
                p[nb][j] = __expf(sqrt_approx(m2));
            }

        // unnormalized attn write
        if (write_attn) {
            float* a0 = attn_r0 + (size_t)kt * BNK;
            float* a1 = attn_r1 + (size_t)kt * BNK;
#pragma unroll
            for (int nb = 0; nb < 8; ++nb) {
                *(float2*)(a0 + nb * 8) = make_float2(p[nb][0], p[nb][1]);
                *(float2*)(a1 + nb * 8) = make_float2(p[nb][2], p[nb][3]);
            }
        }

        // rowsum accumulate
#pragma unroll
        for (int nb = 0; nb < 8; ++nb) {
            rs0 += p[nb][0] + p[nb][1];
            rs1 += p[nb][2] + p[nb][3];
        }

        // ---- O += P @ V : P fragments built directly from p registers ----
        const uint32_t vrb = smb + cur + STG_VR;
        const uint32_t vib = smb + cur + STG_VI;
#pragma unroll
        for (int kb2 = 0; kb2 < 4; ++kb2) {
            uint32_t pa[4];
            pa[0] = packh2(p[2*kb2][0],   p[2*kb2][1]);
            pa[1] = packh2(p[2*kb2][2],   p[2*kb2][3]);
            pa[2] = packh2(p[2*kb2+1][0], p[2*kb2+1][1]);
            pa[3] = packh2(p[2*kb2+1][2], p[2*kb2+1][3]);
            const uint32_t vbase = kb2 * 2048;
#pragma unroll
            for (int nb = 0; nb < 8; ++nb) {
                const uint32_t voff = vbase + ((nb * 16 + rowV) ^ swzV);
                uint32_t vr0, vr1, vi0, vi1;
                ldsm_x2t(vr0, vr1, vrb + voff);
                ldsm_x2t(vi0, vi1, vib + voff);
                mma_f16(o_r[nb], pa, vr0, vr1);
                mma_f16(o_i[nb], pa, vi0, vi1);
            }
        }

        __syncthreads();   // next stage fully written; cur free for overwrite
    }

    // ---- finalize: row sums across the 4 lanes of each row quad ----
    rs0 += __shfl_xor_sync(0xffffffffu, rs0, 1);
    rs0 += __shfl_xor_sync(0xffffffffu, rs0, 2);
    rs1 += __shfl_xor_sync(0xffffffffu, rs1, 1);
    rs1 += __shfl_xor_sync(0xffffffffu, rs1, 2);
    const float inv0 = 1.0f / rs0;
    const float inv1 = 1.0f / rs1;

    if ((l & 3) == 0) {
        g_inv_rowsum[(size_t)bh * LSEQ + arow0]     = inv0;
        g_inv_rowsum[(size_t)bh * LSEQ + arow0 + 8] = inv1;
    }

    if (write_out) {
        float* o0 = Out + ((size_t)bh * LSEQ + arow0) * (DH * 2) + 4 * (l & 3);
        float* o1 = o0 + 8 * (DH * 2);
#pragma unroll
        for (int nb = 0; nb < 8; ++nb) {
            *(float4*)(o0 + nb * 16) = make_float4(o_r[nb][0] * inv0, o_i[nb][0] * inv0,
                                                   o_r[nb][1] * inv0, o_i[nb][1] * inv0);
            *(float4*)(o1 + nb * 16) = make_float4(o_r[nb][2] * inv1, o_i[nb][2] * inv1,
                                                   o_r[nb][3] * inv1, o_i[nb][3] * inv1);
        }
    }
}

// normalize attn in place: one block per (bh, q) row
__global__ void __launch_bounds__(256)
norm_kernel(float* __restrict__ Attn) {
    const size_t row = blockIdx.x;
    const float inv = g_inv_rowsum[row];
    float4* p = (float4*)(Attn + row * LSEQ);
    const int t = threadIdx.x;
#pragma unroll
    for (int i = 0; i < 2; ++i) {
        float4 v = p[t + i * 256];
        v.x *= inv; v.y *= inv; v.z *= inv; v.w *= inv;
        p[t + i * 256] = v;
    }
}

extern "C" void kernel_launch(void* const* d_in, const int* in_sizes, int n_in,
                              void* d_out, int out_size) {
    const float* Qr = (const float*)d_in[0];
    const float* Qi = (const float*)d_in[1];
    const float* Kr = (const float*)d_in[2];
    const float* Ki = (const float*)d_in[3];
    const float* Vr = (const float*)d_in[4];
    const float* Vi = (const float*)d_in[5];

    float* out = (float*)d_out;
    int write_out = 1, write_attn = 1;
    float* attn = out + OUT_ELEMS;

    const size_t os = (size_t)out_size;
    if (os >= OUT_ELEMS + ATTN_ELEMS) {
        // tuple (output, attn) concatenated
    } else if (os == ATTN_ELEMS) {
        write_out = 0;
        attn = out;
    } else {
        write_attn = 0;
        attn = out;  // unused
    }

    cudaFuncSetAttribute(cattn_mma_kernel, cudaFuncAttributeMaxDynamicSharedMemorySize, SMEM_BYTES);

    dim3 grid(QT, NBH);   // q-tiles fastest -> K/V of one (b,h) stay hot in L2
    cattn_mma_kernel<<<grid, 128, SMEM_BYTES>>>(Qr, Qi, Kr, Ki, Vr, Vi,
                                                out, attn, write_out, write_attn);
    if (write_attn) {
        norm_kernel<<<NBH * LSEQ, 256>>>(attn);
    }
}